// round 6
// baseline (speedup 1.0000x reference)
#include <cuda_runtime.h>
#include <cstdint>

#define NTOK   4096
#define DMODEL 1024
#define NEXP   8
#define TOPK   2
#define HEXP   704
#define HSH    1408

#define BM 64
#define BN 64
#define BK 16
#define NTHREADS 256
#define ASTR 68     // As row stride in words
#define BSTR 68     // Bs row stride in words

// ---------------- scratch (device globals; no allocation allowed) ----------
__device__ int   g_cnt[NEXP];
__device__ int   g_off[NEXP + 1];
__device__ int   g_cur[NEXP];
__device__ int   g_topi[NTOK * TOPK];
__device__ float g_topw[NTOK * TOPK];
__device__ int   g_tok[NTOK * TOPK];
__device__ float g_gate[NTOK * TOPK];
__device__ float g_hid_r[NTOK * TOPK * HEXP];   // routed SwiGLU hidden
__device__ float g_hid_s[NTOK * HSH];           // shared-expert hidden

// ---------------- tiny setup kernels ---------------------------------------
__global__ void zero_kernel() {
    int t = threadIdx.x;
    if (t < NEXP) { g_cnt[t] = 0; g_cur[t] = 0; }
}

__global__ void scan_kernel() {
    int acc = 0;
    g_off[0] = 0;
    for (int e = 0; e < NEXP; e++) { acc += g_cnt[e]; g_off[e + 1] = acc; }
}

__global__ void router_kernel(const float* __restrict__ x,
                              const float* __restrict__ Wg) {
    int gw   = (blockIdx.x * blockDim.x + threadIdx.x) >> 5;
    int lane = threadIdx.x & 31;
    if (gw >= NTOK) return;
    const float* xr = x + (size_t)gw * DMODEL;

    float acc[NEXP];
#pragma unroll
    for (int e = 0; e < NEXP; e++) acc[e] = 0.f;
    for (int k = lane; k < DMODEL; k += 32) {
        float xv = xr[k];
#pragma unroll
        for (int e = 0; e < NEXP; e++) acc[e] += xv * Wg[e * DMODEL + k];
    }
#pragma unroll
    for (int e = 0; e < NEXP; e++) {
#pragma unroll
        for (int o = 16; o > 0; o >>= 1)
            acc[e] += __shfl_xor_sync(0xffffffffu, acc[e], o);
    }
    if (lane == 0) {
        float m = acc[0];
#pragma unroll
        for (int e = 1; e < NEXP; e++) m = fmaxf(m, acc[e]);
        float p[NEXP], s = 0.f;
#pragma unroll
        for (int e = 0; e < NEXP; e++) { p[e] = expf(acc[e] - m); s += p[e]; }
        float inv = 1.f / s;
#pragma unroll
        for (int e = 0; e < NEXP; e++) p[e] *= inv;

        int i0 = 0; float v0 = p[0];
#pragma unroll
        for (int e = 1; e < NEXP; e++) if (p[e] > v0) { v0 = p[e]; i0 = e; }
        int i1 = (i0 == 0) ? 1 : 0; float v1 = p[i1];
#pragma unroll
        for (int e = 0; e < NEXP; e++)
            if (e != i0 && p[e] > v1) { v1 = p[e]; i1 = e; }

        float sw = v0 + v1 + 1e-20f;
        g_topi[gw * 2] = i0;  g_topi[gw * 2 + 1] = i1;
        g_topw[gw * 2] = v0 / sw;  g_topw[gw * 2 + 1] = v1 / sw;
        atomicAdd(&g_cnt[i0], 1);
        atomicAdd(&g_cnt[i1], 1);
    }
}

__global__ void fill_kernel() {
    int n = blockIdx.x * blockDim.x + threadIdx.x;
    if (n >= NTOK) return;
#pragma unroll
    for (int s = 0; s < TOPK; s++) {
        int e   = g_topi[n * 2 + s];
        int pos = atomicAdd(&g_cur[e], 1);
        int idx = g_off[e] + pos;
        g_tok[idx]  = n;
        g_gate[idx] = g_topw[n * 2 + s];
    }
}

__device__ __forceinline__ float silu_f(float z) {
    return z / (1.f + __expf(-z));
}
__device__ __forceinline__ uint32_t f2tf32(float f) {
    uint32_t u;
    asm("cvt.rna.tf32.f32 %0, %1;" : "=r"(u) : "f"(f));
    return u;
}
__device__ __forceinline__ void mma_tf32(float* c, const uint32_t* a,
                                         uint32_t b0, uint32_t b1) {
    asm volatile(
        "mma.sync.aligned.m16n8k8.row.col.f32.tf32.tf32.f32 "
        "{%0,%1,%2,%3}, {%4,%5,%6,%7}, {%8,%9}, {%0,%1,%2,%3};\n"
        : "+f"(c[0]), "+f"(c[1]), "+f"(c[2]), "+f"(c[3])
        : "r"(a[0]), "r"(a[1]), "r"(a[2]), "r"(a[3]), "r"(b0), "r"(b1));
}

// ============ GEMM1: hid = silu(A@W1)*(A@W3).  CTA 64x64, BK=16 =============
// 8 warps = 2(m) x 4(n); warp tile 32x16 => per warp 2 m16 x 2 n8 frags.
template<bool ROUTED>
__global__ __launch_bounds__(NTHREADS)
void swiglu_mma(const float* __restrict__ x,
                const float* __restrict__ W1g,
                const float* __restrict__ W3g,
                float* __restrict__ hid, int H) {
    int e = 0, base = 0, ne = NTOK;
    if (ROUTED) { e = blockIdx.z; base = g_off[e]; ne = g_off[e + 1] - base; }
    int m0 = blockIdx.y * BM;
    if (m0 >= ne) return;
    int n0 = blockIdx.x * BN;

    const float* W1 = W1g + (ROUTED ? (size_t)e * DMODEL * H : 0) + n0;
    const float* W3 = W3g + (ROUTED ? (size_t)e * DMODEL * H : 0) + n0;

    __shared__ uint32_t As[BK][ASTR];    // [k][m]
    __shared__ uint32_t Bs1[BK][BSTR];   // [k][n]
    __shared__ uint32_t Bs3[BK][BSTR];
    __shared__ int      stok[BM];

    int tid = threadIdx.x;
    if (ROUTED) {
        if (tid < BM) stok[tid] = (m0 + tid < ne) ? g_tok[base + m0 + tid] : -1;
        __syncthreads();
    }

    // A loader: row = tid>>2, k-quad = (tid&3)*4
    int ar = tid >> 2, ac = (tid & 3) * 4;
    bool aok;
    const float* Arow;
    if (ROUTED) {
        int tk = stok[ar];
        aok  = (tk >= 0);
        Arow = x + (size_t)(aok ? tk : 0) * DMODEL;
    } else {
        aok  = true;
        Arow = x + (size_t)(m0 + ar) * DMODEL;
    }
    // B loader: k = tid>>4, n-quad = (tid&15)*4
    int bk = tid >> 4, bn = (tid & 15) * 4;

    float4 av  = aok ? *(const float4*)(Arow + ac) : make_float4(0, 0, 0, 0);
    float4 b1v = *(const float4*)(W1 + (size_t)bk * H + bn);
    float4 b3v = *(const float4*)(W3 + (size_t)bk * H + bn);

    int lane = tid & 31, wid = tid >> 5;
    int mw = (wid & 1) * 32, nw = (wid >> 1) * 16;
    int g = lane >> 2, tq = lane & 3;

    float acc1[2][2][4], acc3[2][2][4];
#pragma unroll
    for (int i = 0; i < 2; i++)
#pragma unroll
        for (int j = 0; j < 2; j++)
#pragma unroll
            for (int k = 0; k < 4; k++) { acc1[i][j][k] = 0.f; acc3[i][j][k] = 0.f; }

    for (int kk = 0; kk < DMODEL; kk += BK) {
        As[ac + 0][ar] = f2tf32(av.x);
        As[ac + 1][ar] = f2tf32(av.y);
        As[ac + 2][ar] = f2tf32(av.z);
        As[ac + 3][ar] = f2tf32(av.w);
        Bs1[bk][bn + 0] = f2tf32(b1v.x);
        Bs1[bk][bn + 1] = f2tf32(b1v.y);
        Bs1[bk][bn + 2] = f2tf32(b1v.z);
        Bs1[bk][bn + 3] = f2tf32(b1v.w);
        Bs3[bk][bn + 0] = f2tf32(b3v.x);
        Bs3[bk][bn + 1] = f2tf32(b3v.y);
        Bs3[bk][bn + 2] = f2tf32(b3v.z);
        Bs3[bk][bn + 3] = f2tf32(b3v.w);
        __syncthreads();

        int kn = kk + BK;
        if (kn < DMODEL) {
            if (aok) av = *(const float4*)(Arow + kn + ac);
            b1v = *(const float4*)(W1 + (size_t)(kn + bk) * H + bn);
            b3v = *(const float4*)(W3 + (size_t)(kn + bk) * H + bn);
        }

#pragma unroll
        for (int ks = 0; ks < 2; ks++) {
            int k0 = ks * 8;
            uint32_t a[2][4];
#pragma unroll
            for (int mt = 0; mt < 2; mt++) {
                int r = mw + mt * 16 + g;
                a[mt][0] = As[k0 + tq][r];
                a[mt][1] = As[k0 + tq][r + 8];
                a[mt][2] = As[k0 + tq + 4][r];
                a[mt][3] = As[k0 + tq + 4][r + 8];
            }
#pragma unroll
            for (int nt = 0; nt < 2; nt++) {
                int c = nw + nt * 8 + g;
                uint32_t p0 = Bs1[k0 + tq][c];
                uint32_t p1 = Bs1[k0 + tq + 4][c];
                uint32_t q0 = Bs3[k0 + tq][c];
                uint32_t q1 = Bs3[k0 + tq + 4][c];
#pragma unroll
                for (int mt = 0; mt < 2; mt++) {
                    mma_tf32(acc1[mt][nt], a[mt], p0, p1);
                    mma_tf32(acc3[mt][nt], a[mt], q0, q1);
                }
            }
        }
        __syncthreads();
    }

    // epilogue: c0,c1 -> row g; c2,c3 -> row g+8; cols 2tq,2tq+1
#pragma unroll
    for (int mt = 0; mt < 2; mt++) {
#pragma unroll
        for (int h = 0; h < 2; h++) {
            int r = mw + mt * 16 + g + h * 8;
            if (!ROUTED || (m0 + r < ne)) {
                size_t rowoff = (size_t)(base + m0 + r) * H + n0;
#pragma unroll
                for (int nt = 0; nt < 2; nt++) {
                    int col = nw + nt * 8 + 2 * tq;
                    float2 v;
                    v.x = silu_f(acc1[mt][nt][2 * h])     * acc3[mt][nt][2 * h];
                    v.y = silu_f(acc1[mt][nt][2 * h + 1]) * acc3[mt][nt][2 * h + 1];
                    *(float2*)&hid[rowoff + col] = v;
                }
            }
        }
    }
}

// ============ GEMM2: out (+)= [gate *] (hid @ W2).  CTA 64x64, BK=16 ========
template<bool ROUTED>
__global__ __launch_bounds__(NTHREADS)
void down_mma(const float* __restrict__ hidg,
              const float* __restrict__ W2g,
              float* __restrict__ out, int K) {
    int e = 0, base = 0, ne = NTOK;
    if (ROUTED) { e = blockIdx.z; base = g_off[e]; ne = g_off[e + 1] - base; }
    int m0 = blockIdx.y * BM;
    if (m0 >= ne) return;
    int n0 = blockIdx.x * BN;

    const float* W2 = W2g + (ROUTED ? (size_t)e * K * DMODEL : 0) + n0;

    __shared__ uint32_t As[BK][ASTR];
    __shared__ uint32_t Bs[BK][BSTR];
    __shared__ int      stok[BM];
    __shared__ float    sgate[BM];

    int tid = threadIdx.x;
    if (ROUTED) {
        if (tid < BM) {
            bool v = (m0 + tid < ne);
            stok[tid]  = v ? g_tok[base + m0 + tid] : 0;
            sgate[tid] = v ? g_gate[base + m0 + tid] : 0.f;
        }
        __syncthreads();
    }

    int ar = tid >> 2, ac = (tid & 3) * 4;
    bool aok = (m0 + ar < ne);
    const float* Arow = hidg + (size_t)(base + m0 + (aok ? ar : 0)) * K;
    int bk = tid >> 4, bn = (tid & 15) * 4;

    float4 av = aok ? *(const float4*)(Arow + ac) : make_float4(0, 0, 0, 0);
    float4 bv = *(const float4*)(W2 + (size_t)bk * DMODEL + bn);

    int lane = tid & 31, wid = tid >> 5;
    int mw = (wid & 1) * 32, nw = (wid >> 1) * 16;
    int g = lane >> 2, tq = lane & 3;

    float acc[2][2][4];
#pragma unroll
    for (int i = 0; i < 2; i++)
#pragma unroll
        for (int j = 0; j < 2; j++)
#pragma unroll
            for (int k = 0; k < 4; k++) acc[i][j][k] = 0.f;

    for (int kk = 0; kk < K; kk += BK) {
        As[ac + 0][ar] = f2tf32(av.x);
        As[ac + 1][ar] = f2tf32(av.y);
        As[ac + 2][ar] = f2tf32(av.z);
        As[ac + 3][ar] = f2tf32(av.w);
        Bs[bk][bn + 0] = f2tf32(bv.x);
        Bs[bk][bn + 1] = f2tf32(bv.y);
        Bs[bk][bn + 2] = f2tf32(bv.z);
        Bs[bk][bn + 3] = f2tf32(bv.w);
        __syncthreads();

        int kn = kk + BK;
        if (kn < K) {
            if (aok) av = *(const float4*)(Arow + kn + ac);
            bv = *(const float4*)(W2 + (size_t)(kn + bk) * DMODEL + bn);
        }

#pragma unroll
        for (int ks = 0; ks < 2; ks++) {
            int k0 = ks * 8;
            uint32_t a[2][4];
#pragma unroll
            for (int mt = 0; mt < 2; mt++) {
                int r = mw + mt * 16 + g;
                a[mt][0] = As[k0 + tq][r];
                a[mt][1] = As[k0 + tq][r + 8];
                a[mt][2] = As[k0 + tq + 4][r];
                a[mt][3] = As[k0 + tq + 4][r + 8];
            }
#pragma unroll
            for (int nt = 0; nt < 2; nt++) {
                int c = nw + nt * 8 + g;
                uint32_t p0 = Bs[k0 + tq][c];
                uint32_t p1 = Bs[k0 + tq + 4][c];
#pragma unroll
                for (int mt = 0; mt < 2; mt++)
                    mma_tf32(acc[mt][nt], a[mt], p0, p1);
            }
        }
        __syncthreads();
    }

#pragma unroll
    for (int mt = 0; mt < 2; mt++) {
#pragma unroll
        for (int h = 0; h < 2; h++) {
            int r = mw + mt * 16 + g + h * 8;
            if (ROUTED) {
                if (m0 + r < ne) {
                    int   tk = stok[r];
                    float w  = sgate[r];
                    float* op = out + (size_t)tk * DMODEL + n0;
#pragma unroll
                    for (int nt = 0; nt < 2; nt++) {
                        int col = nw + nt * 8 + 2 * tq;
                        atomicAdd(op + col,     w * acc[mt][nt][2 * h]);
                        atomicAdd(op + col + 1, w * acc[mt][nt][2 * h + 1]);
                    }
                }
            } else {
                size_t rowoff = (size_t)(m0 + r) * DMODEL + n0;
#pragma unroll
                for (int nt = 0; nt < 2; nt++) {
                    int col = nw + nt * 8 + 2 * tq;
                    float2 v;
                    v.x = acc[mt][nt][2 * h];
                    v.y = acc[mt][nt][2 * h + 1];
                    *(float2*)&out[rowoff + col] = v;
                }
            }
        }
    }
}

// ---------------- launch -----------------------------------------------------
extern "C" void kernel_launch(void* const* d_in, const int* in_sizes, int n_in,
                              void* d_out, int out_size) {
    const float* x   = (const float*)d_in[0];
    const float* Wg  = (const float*)d_in[1];
    const float* W1  = (const float*)d_in[2];
    const float* W3  = (const float*)d_in[3];
    const float* W2  = (const float*)d_in[4];
    const float* Ws1 = (const float*)d_in[5];
    const float* Ws3 = (const float*)d_in[6];
    const float* Ws2 = (const float*)d_in[7];
    float* out = (float*)d_out;

    zero_kernel<<<1, 32>>>();
    router_kernel<<<NTOK / 8, 256>>>(x, Wg);
    scan_kernel<<<1, 1>>>();
    fill_kernel<<<NTOK / 256, 256>>>();

    // shared expert (writes every element of out) must precede routed scatter
    swiglu_mma<false><<<dim3(HSH / BN, NTOK / BM), NTHREADS>>>(x, Ws1, Ws3, g_hid_s, HSH);
    down_mma<false><<<dim3(DMODEL / BN, NTOK / BM), NTHREADS>>>(g_hid_s, Ws2, out, HSH);

    swiglu_mma<true><<<dim3(HEXP / BN, NTOK / BM, NEXP), NTHREADS>>>(x, W1, W3, g_hid_r, HEXP);
    down_mma<true><<<dim3(DMODEL / BN, NTOK / BM, NEXP), NTHREADS>>>(g_hid_r, W2, out, HEXP);
}

// round 7
// speedup vs baseline: 1.0895x; 1.0895x over previous
#include <cuda_runtime.h>
#include <cuda_fp16.h>
#include <cstdint>

#define NTOK   4096
#define DMODEL 1024
#define NEXP   8
#define TOPK   2
#define HEXP   704
#define HSH    1408

#define BM 64
#define BN 64
#define BK 16
#define NTHREADS 256
#define ASTRW 12    // As row stride in half2-words (conflict-free frag reads)
#define BSTRW 68    // Bs row stride in half2-words

// ---------------- scratch (device globals; no allocation allowed) ----------
__device__ int   g_cnt[NEXP];
__device__ int   g_off[NEXP + 1];
__device__ int   g_cur[NEXP];
__device__ int   g_topi[NTOK * TOPK];
__device__ float g_topw[NTOK * TOPK];
__device__ int   g_tok[NTOK * TOPK];
__device__ float g_gate[NTOK * TOPK];
__device__ float g_hid_r[NTOK * TOPK * HEXP];   // routed SwiGLU hidden
__device__ float g_hid_s[NTOK * HSH];           // shared-expert hidden

// ---------------- tiny setup kernels ---------------------------------------
__global__ void zero_kernel() {
    int t = threadIdx.x;
    if (t < NEXP) { g_cnt[t] = 0; g_cur[t] = 0; }
}

__global__ void scan_kernel() {
    int acc = 0;
    g_off[0] = 0;
    for (int e = 0; e < NEXP; e++) { acc += g_cnt[e]; g_off[e + 1] = acc; }
}

__global__ void router_kernel(const float* __restrict__ x,
                              const float* __restrict__ Wg) {
    int gw   = (blockIdx.x * blockDim.x + threadIdx.x) >> 5;
    int lane = threadIdx.x & 31;
    if (gw >= NTOK) return;
    const float* xr = x + (size_t)gw * DMODEL;

    float acc[NEXP];
#pragma unroll
    for (int e = 0; e < NEXP; e++) acc[e] = 0.f;
    for (int k = lane; k < DMODEL; k += 32) {
        float xv = xr[k];
#pragma unroll
        for (int e = 0; e < NEXP; e++) acc[e] += xv * Wg[e * DMODEL + k];
    }
#pragma unroll
    for (int e = 0; e < NEXP; e++) {
#pragma unroll
        for (int o = 16; o > 0; o >>= 1)
            acc[e] += __shfl_xor_sync(0xffffffffu, acc[e], o);
    }
    if (lane == 0) {
        float m = acc[0];
#pragma unroll
        for (int e = 1; e < NEXP; e++) m = fmaxf(m, acc[e]);
        float p[NEXP], s = 0.f;
#pragma unroll
        for (int e = 0; e < NEXP; e++) { p[e] = expf(acc[e] - m); s += p[e]; }
        float inv = 1.f / s;
#pragma unroll
        for (int e = 0; e < NEXP; e++) p[e] *= inv;

        int i0 = 0; float v0 = p[0];
#pragma unroll
        for (int e = 1; e < NEXP; e++) if (p[e] > v0) { v0 = p[e]; i0 = e; }
        int i1 = (i0 == 0) ? 1 : 0; float v1 = p[i1];
#pragma unroll
        for (int e = 0; e < NEXP; e++)
            if (e != i0 && p[e] > v1) { v1 = p[e]; i1 = e; }

        float sw = v0 + v1 + 1e-20f;
        g_topi[gw * 2] = i0;  g_topi[gw * 2 + 1] = i1;
        g_topw[gw * 2] = v0 / sw;  g_topw[gw * 2 + 1] = v1 / sw;
        atomicAdd(&g_cnt[i0], 1);
        atomicAdd(&g_cnt[i1], 1);
    }
}

__global__ void fill_kernel() {
    int n = blockIdx.x * blockDim.x + threadIdx.x;
    if (n >= NTOK) return;
#pragma unroll
    for (int s = 0; s < TOPK; s++) {
        int e   = g_topi[n * 2 + s];
        int pos = atomicAdd(&g_cur[e], 1);
        int idx = g_off[e] + pos;
        g_tok[idx]  = n;
        g_gate[idx] = g_topw[n * 2 + s];
    }
}

__device__ __forceinline__ float silu_f(float z) {
    return z / (1.f + __expf(-z));
}
// pack two floats into half2 word: LOW half = first arg (= even k index)
__device__ __forceinline__ uint32_t f2h2(float lo, float hi) {
    __half2 h = __floats2half2_rn(lo, hi);
    return *reinterpret_cast<uint32_t*>(&h);
}
__device__ __forceinline__ void mma_f16(float* c, const uint32_t* a,
                                        uint32_t b0, uint32_t b1) {
    asm volatile(
        "mma.sync.aligned.m16n8k16.row.col.f32.f16.f16.f32 "
        "{%0,%1,%2,%3}, {%4,%5,%6,%7}, {%8,%9}, {%0,%1,%2,%3};\n"
        : "+f"(c[0]), "+f"(c[1]), "+f"(c[2]), "+f"(c[3])
        : "r"(a[0]), "r"(a[1]), "r"(a[2]), "r"(a[3]), "r"(b0), "r"(b1));
}

// ============ GEMM1: hid = silu(A@W1)*(A@W3).  CTA 64x64, BK=16 =============
// 8 warps = 2(m) x 4(n); warp tile 32x16 -> 2 m16 x 2 n8 frags, 1 k16 step/tile
template<bool ROUTED>
__global__ __launch_bounds__(NTHREADS)
void swiglu_hmma(const float* __restrict__ x,
                 const float* __restrict__ W1g,
                 const float* __restrict__ W3g,
                 float* __restrict__ hid, int H) {
    int e = 0, base = 0, ne = NTOK;
    if (ROUTED) { e = blockIdx.z; base = g_off[e]; ne = g_off[e + 1] - base; }
    int m0 = blockIdx.y * BM;
    if (m0 >= ne) return;
    int n0 = blockIdx.x * BN;

    const float* W1 = W1g + (ROUTED ? (size_t)e * DMODEL * H : 0) + n0;
    const float* W3 = W3g + (ROUTED ? (size_t)e * DMODEL * H : 0) + n0;

    // half2 words: As[m][k/2], Bs[mat][k/2][n]
    __shared__ uint32_t As[BM][ASTRW];
    __shared__ uint32_t Bs[2][BK / 2][BSTRW];
    __shared__ int      stok[BM];

    int tid = threadIdx.x;
    if (ROUTED) {
        if (tid < BM) stok[tid] = (m0 + tid < ne) ? g_tok[base + m0 + tid] : -1;
        __syncthreads();
    }

    // A loader: row = tid>>2, k-quad = (tid&3)*4 floats -> 2 half2 words
    int ar = tid >> 2, acw = (tid & 3) * 2;
    bool aok;
    const float* Arow;
    if (ROUTED) {
        int tk = stok[ar];
        aok  = (tk >= 0);
        Arow = x + (size_t)(aok ? tk : 0) * DMODEL;
    } else {
        aok  = true;
        Arow = x + (size_t)(m0 + ar) * DMODEL;
    }
    // B loader: tid>>7 selects matrix; within 128: k-pair j = t>>4, n quad
    int bmat = tid >> 7;
    int bt   = tid & 127;
    int bj   = bt >> 4;
    int bn   = (bt & 15) * 4;
    const float* Bsrc = (bmat ? W3 : W1) + bn;

    float4 av  = aok ? *(const float4*)(Arow + acw * 2) : make_float4(0, 0, 0, 0);
    float4 bv0 = *(const float4*)(Bsrc + (size_t)(2 * bj)     * H);
    float4 bv1 = *(const float4*)(Bsrc + (size_t)(2 * bj + 1) * H);

    int lane = tid & 31, wid = tid >> 5;
    int mw = (wid & 1) * 32, nw = (wid >> 1) * 16;
    int g = lane >> 2, tq = lane & 3;

    float acc1[2][2][4], acc3[2][2][4];
#pragma unroll
    for (int i = 0; i < 2; i++)
#pragma unroll
        for (int j = 0; j < 2; j++)
#pragma unroll
            for (int k = 0; k < 4; k++) { acc1[i][j][k] = 0.f; acc3[i][j][k] = 0.f; }

    for (int kk = 0; kk < DMODEL; kk += BK) {
        As[ar][acw]     = f2h2(av.x, av.y);
        As[ar][acw + 1] = f2h2(av.z, av.w);
        Bs[bmat][bj][bn + 0] = f2h2(bv0.x, bv1.x);
        Bs[bmat][bj][bn + 1] = f2h2(bv0.y, bv1.y);
        Bs[bmat][bj][bn + 2] = f2h2(bv0.z, bv1.z);
        Bs[bmat][bj][bn + 3] = f2h2(bv0.w, bv1.w);
        __syncthreads();

        int kn = kk + BK;
        if (kn < DMODEL) {
            if (aok) av = *(const float4*)(Arow + kn + acw * 2);
            bv0 = *(const float4*)(Bsrc + (size_t)(kn + 2 * bj)     * H);
            bv1 = *(const float4*)(Bsrc + (size_t)(kn + 2 * bj + 1) * H);
        }

        // one m16n8k16 step covers the whole BK=16 tile
        uint32_t a[2][4];
#pragma unroll
        for (int mt = 0; mt < 2; mt++) {
            int r = mw + mt * 16 + g;
            a[mt][0] = As[r][tq];
            a[mt][1] = As[r + 8][tq];
            a[mt][2] = As[r][tq + 4];
            a[mt][3] = As[r + 8][tq + 4];
        }
#pragma unroll
        for (int nt = 0; nt < 2; nt++) {
            int c = nw + nt * 8 + g;
            uint32_t p0 = Bs[0][tq][c];
            uint32_t p1 = Bs[0][tq + 4][c];
            uint32_t q0 = Bs[1][tq][c];
            uint32_t q1 = Bs[1][tq + 4][c];
#pragma unroll
            for (int mt = 0; mt < 2; mt++) {
                mma_f16(acc1[mt][nt], a[mt], p0, p1);
                mma_f16(acc3[mt][nt], a[mt], q0, q1);
            }
        }
        __syncthreads();
    }

#pragma unroll
    for (int mt = 0; mt < 2; mt++) {
#pragma unroll
        for (int h = 0; h < 2; h++) {
            int r = mw + mt * 16 + g + h * 8;
            if (!ROUTED || (m0 + r < ne)) {
                size_t rowoff = (size_t)(base + m0 + r) * H + n0;
#pragma unroll
                for (int nt = 0; nt < 2; nt++) {
                    int col = nw + nt * 8 + 2 * tq;
                    float2 v;
                    v.x = silu_f(acc1[mt][nt][2 * h])     * acc3[mt][nt][2 * h];
                    v.y = silu_f(acc1[mt][nt][2 * h + 1]) * acc3[mt][nt][2 * h + 1];
                    *(float2*)&hid[rowoff + col] = v;
                }
            }
        }
    }
}

// ============ GEMM2: out (+)= [gate *] (hid @ W2).  CTA 64x64, BK=16 ========
template<bool ROUTED>
__global__ __launch_bounds__(NTHREADS)
void down_hmma(const float* __restrict__ hidg,
               const float* __restrict__ W2g,
               float* __restrict__ out, int K) {
    int e = 0, base = 0, ne = NTOK;
    if (ROUTED) { e = blockIdx.z; base = g_off[e]; ne = g_off[e + 1] - base; }
    int m0 = blockIdx.y * BM;
    if (m0 >= ne) return;
    int n0 = blockIdx.x * BN;

    const float* W2 = W2g + (ROUTED ? (size_t)e * K * DMODEL : 0) + n0;

    __shared__ uint32_t As[BM][ASTRW];
    __shared__ uint32_t Bs[BK / 2][BSTRW];
    __shared__ int      stok[BM];
    __shared__ float    sgate[BM];

    int tid = threadIdx.x;
    if (ROUTED) {
        if (tid < BM) {
            bool v = (m0 + tid < ne);
            stok[tid]  = v ? g_tok[base + m0 + tid] : 0;
            sgate[tid] = v ? g_gate[base + m0 + tid] : 0.f;
        }
        __syncthreads();
    }

    int ar = tid >> 2, acw = (tid & 3) * 2;
    bool aok = (m0 + ar < ne);
    const float* Arow = hidg + (size_t)(base + m0 + (aok ? ar : 0)) * K;
    // B loader: threads < 128
    int bj = (tid & 127) >> 4;
    int bn = (tid & 15) * 4;
    bool bload = (tid < 128);

    float4 av  = aok ? *(const float4*)(Arow + acw * 2) : make_float4(0, 0, 0, 0);
    float4 bv0 = make_float4(0, 0, 0, 0), bv1 = make_float4(0, 0, 0, 0);
    if (bload) {
        bv0 = *(const float4*)(W2 + (size_t)(2 * bj)     * DMODEL + bn);
        bv1 = *(const float4*)(W2 + (size_t)(2 * bj + 1) * DMODEL + bn);
    }

    int lane = tid & 31, wid = tid >> 5;
    int mw = (wid & 1) * 32, nw = (wid >> 1) * 16;
    int g = lane >> 2, tq = lane & 3;

    float acc[2][2][4];
#pragma unroll
    for (int i = 0; i < 2; i++)
#pragma unroll
        for (int j = 0; j < 2; j++)
#pragma unroll
            for (int k = 0; k < 4; k++) acc[i][j][k] = 0.f;

    for (int kk = 0; kk < K; kk += BK) {
        As[ar][acw]     = f2h2(av.x, av.y);
        As[ar][acw + 1] = f2h2(av.z, av.w);
        if (bload) {
            Bs[bj][bn + 0] = f2h2(bv0.x, bv1.x);
            Bs[bj][bn + 1] = f2h2(bv0.y, bv1.y);
            Bs[bj][bn + 2] = f2h2(bv0.z, bv1.z);
            Bs[bj][bn + 3] = f2h2(bv0.w, bv1.w);
        }
        __syncthreads();

        int kn = kk + BK;
        if (kn < K) {
            if (aok) av = *(const float4*)(Arow + kn + acw * 2);
            if (bload) {
                bv0 = *(const float4*)(W2 + (size_t)(kn + 2 * bj)     * DMODEL + bn);
                bv1 = *(const float4*)(W2 + (size_t)(kn + 2 * bj + 1) * DMODEL + bn);
            }
        }

        uint32_t a[2][4];
#pragma unroll
        for (int mt = 0; mt < 2; mt++) {
            int r = mw + mt * 16 + g;
            a[mt][0] = As[r][tq];
            a[mt][1] = As[r + 8][tq];
            a[mt][2] = As[r][tq + 4];
            a[mt][3] = As[r + 8][tq + 4];
        }
#pragma unroll
        for (int nt = 0; nt < 2; nt++) {
            int c = nw + nt * 8 + g;
            uint32_t p0 = Bs[tq][c];
            uint32_t p1 = Bs[tq + 4][c];
#pragma unroll
            for (int mt = 0; mt < 2; mt++)
                mma_f16(acc[mt][nt], a[mt], p0, p1);
        }
        __syncthreads();
    }

#pragma unroll
    for (int mt = 0; mt < 2; mt++) {
#pragma unroll
        for (int h = 0; h < 2; h++) {
            int r = mw + mt * 16 + g + h * 8;
            if (ROUTED) {
                if (m0 + r < ne) {
                    int   tk = stok[r];
                    float w  = sgate[r];
                    float* op = out + (size_t)tk * DMODEL + n0;
#pragma unroll
                    for (int nt = 0; nt < 2; nt++) {
                        int col = nw + nt * 8 + 2 * tq;
                        atomicAdd(op + col,     w * acc[mt][nt][2 * h]);
                        atomicAdd(op + col + 1, w * acc[mt][nt][2 * h + 1]);
                    }
                }
            } else {
                size_t rowoff = (size_t)(m0 + r) * DMODEL + n0;
#pragma unroll
                for (int nt = 0; nt < 2; nt++) {
                    int col = nw + nt * 8 + 2 * tq;
                    float2 v;
                    v.x = acc[mt][nt][2 * h];
                    v.y = acc[mt][nt][2 * h + 1];
                    *(float2*)&out[rowoff + col] = v;
                }
            }
        }
    }
}

// ---------------- launch -----------------------------------------------------
extern "C" void kernel_launch(void* const* d_in, const int* in_sizes, int n_in,
                              void* d_out, int out_size) {
    const float* x   = (const float*)d_in[0];
    const float* Wg  = (const float*)d_in[1];
    const float* W1  = (const float*)d_in[2];
    const float* W3  = (const float*)d_in[3];
    const float* W2  = (const float*)d_in[4];
    const float* Ws1 = (const float*)d_in[5];
    const float* Ws3 = (const float*)d_in[6];
    const float* Ws2 = (const float*)d_in[7];
    float* out = (float*)d_out;

    zero_kernel<<<1, 32>>>();
    router_kernel<<<NTOK / 8, 256>>>(x, Wg);
    scan_kernel<<<1, 1>>>();
    fill_kernel<<<NTOK / 256, 256>>>();

    // shared expert (writes every element of out) must precede routed scatter
    swiglu_hmma<false><<<dim3(HSH / BN, NTOK / BM), NTHREADS>>>(x, Ws1, Ws3, g_hid_s, HSH);
    down_hmma<false><<<dim3(DMODEL / BN, NTOK / BM), NTHREADS>>>(g_hid_s, Ws2, out, HSH);

    swiglu_hmma<true><<<dim3(HEXP / BN, NTOK / BM, NEXP), NTHREADS>>>(x, W1, W3, g_hid_r, HEXP);
    down_hmma<true><<<dim3(DMODEL / BN, NTOK / BM, NEXP), NTHREADS>>>(g_hid_r, W2, out, HEXP);
}